// round 2
// baseline (speedup 1.0000x reference)
#include <cuda_runtime.h>
#include <math.h>

#define BATCH  2
#define TSEQ   2048
#define BT     (BATCH*TSEQ)   // 4096
#define DMODEL 1024
#define NHEAD  16
#define DHEAD  64
#define VOCAB  32000

// ---------------- scratch (device globals; referenced ONLY from device code) ----
__device__ __align__(16) int   g_cnt[VOCAB];
__device__ __align__(16) float g_m[3][DMODEL];   // 0: r-mix, 1: k-mix, 2: v-mix
__device__ __align__(16) float g_r[BT*DMODEL];
__device__ __align__(16) float g_k[BT*DMODEL];
__device__ __align__(16) float g_v[BT*DMODEL];
__device__ __align__(16) float g_o[BT*DMODEL];

// ---------------- kWTA: histogram + top-5 + gains ----------------
__global__ void zero_cnt_kernel() {
    int i = blockIdx.x * blockDim.x + threadIdx.x;
    if (i < VOCAB) g_cnt[i] = 0;
}

__global__ void hist_kernel(const int* __restrict__ tok) {
    int i = blockIdx.x * blockDim.x + threadIdx.x;   // grid covers exactly BT
    atomicAdd(&g_cnt[tok[i]], 1);
}

// Single block. 5 sequential argmax passes with key = (count<<16)|(V-1-i)
// -> max count first, ties broken toward LOWER index (matches jax.lax.top_k).
__global__ void topk_gains_kernel(const float* __restrict__ tmr,
                                  const float* __restrict__ tmk,
                                  const float* __restrict__ tmv) {
    __shared__ long long skey[256];
    __shared__ int sel[5];
    int tid = threadIdx.x;
    for (int it = 0; it < 5; it++) {
        long long best = -1;
        for (int i = tid; i < VOCAB; i += 256) {
            bool ex = false;
            for (int j = 0; j < it; j++) if (sel[j] == i) ex = true;
            if (ex) continue;
            long long key = (((long long)g_cnt[i]) << 16) | (long long)(VOCAB - 1 - i);
            if (key > best) best = key;
        }
        skey[tid] = best;
        __syncthreads();
        for (int s = 128; s > 0; s >>= 1) {
            if (tid < s && skey[tid + s] > skey[tid]) skey[tid] = skey[tid + s];
            __syncthreads();
        }
        if (tid == 0) sel[it] = VOCAB - 1 - (int)(skey[0] & 0xFFFFLL);
        __syncthreads();
    }
    for (int d = tid; d < DMODEL; d += 256) {
        float g = (g_cnt[d] > 0) ? 0.6f : 1.0f;
        #pragma unroll
        for (int j = 0; j < 5; j++) if (sel[j] == d) g = 1.5f;
        g_m[0][d] = tmr[d] * g;
        g_m[1][d] = tmk[d] * g;
        g_m[2][d] = tmv[d] * g;
    }
}

// ---------------- fused GEMM: C[4096,1024] = A @ W^T ----------------
// MODE 0/1/2: A = m*x + (1-m)*prev_x (token shift); writes g_r/g_k/g_v
//             (selected in DEVICE code -- device globals never cross the
//              launch boundary). Epilogue MODE 1 -> spike (>0.5).
// MODE 3:     A = sigmoid(g_r) * g_o ; writes Cout (harness d_out) + bias.
template<int MODE>
__global__ __launch_bounds__(256)
void gemm_kernel(const float* __restrict__ X,
                 const float* __restrict__ W,
                 const float* __restrict__ bias,
                 float* __restrict__ Cout)
{
    float* C;
    if      (MODE == 0) C = g_r;
    else if (MODE == 1) C = g_k;
    else if (MODE == 2) C = g_v;
    else                C = Cout;

    __shared__ __align__(16) float As[8][128];
    __shared__ __align__(16) float Ws[8][128];
    const int bm = blockIdx.y * 128;
    const int bn = blockIdx.x * 128;
    const int tid = threadIdx.x;
    const int lr  = tid >> 1;           // 0..127 (tile row to load)
    const int lc  = (tid & 1) * 4;      // 0 or 4 (k offset, float4)
    const int tx  = tid & 15;
    const int ty  = tid >> 4;

    float acc[8][8];
    #pragma unroll
    for (int i = 0; i < 8; i++)
        #pragma unroll
        for (int j = 0; j < 8; j++) acc[i][j] = 0.f;

    for (int k0 = 0; k0 < DMODEL; k0 += 8) {
        // ---- A tile (fused prologue) ----
        {
            int t = bm + lr;
            int d = k0 + lc;
            float4 a;
            if (MODE < 3) {
                float4 xv = *(const float4*)(X + (size_t)t * DMODEL + d);
                float4 pv = make_float4(0.f, 0.f, 0.f, 0.f);
                if ((t & (TSEQ - 1)) != 0)
                    pv = *(const float4*)(X + (size_t)(t - 1) * DMODEL + d);
                float4 mv = *(const float4*)(&g_m[MODE][d]);
                a.x = mv.x * xv.x + (1.f - mv.x) * pv.x;
                a.y = mv.y * xv.y + (1.f - mv.y) * pv.y;
                a.z = mv.z * xv.z + (1.f - mv.z) * pv.z;
                a.w = mv.w * xv.w + (1.f - mv.w) * pv.w;
            } else {
                float4 rv = *(const float4*)(g_r + (size_t)t * DMODEL + d);
                float4 ov = *(const float4*)(g_o + (size_t)t * DMODEL + d);
                a.x = ov.x / (1.f + __expf(-rv.x));
                a.y = ov.y / (1.f + __expf(-rv.y));
                a.z = ov.z / (1.f + __expf(-rv.z));
                a.w = ov.w / (1.f + __expf(-rv.w));
            }
            As[lc + 0][lr] = a.x; As[lc + 1][lr] = a.y;
            As[lc + 2][lr] = a.z; As[lc + 3][lr] = a.w;

            float4 w = *(const float4*)(W + (size_t)(bn + lr) * DMODEL + k0 + lc);
            Ws[lc + 0][lr] = w.x; Ws[lc + 1][lr] = w.y;
            Ws[lc + 2][lr] = w.z; Ws[lc + 3][lr] = w.w;
        }
        __syncthreads();
        #pragma unroll
        for (int kk = 0; kk < 8; kk++) {
            float4 a0 = *(const float4*)&As[kk][ty * 8];
            float4 a1 = *(const float4*)&As[kk][ty * 8 + 4];
            float4 w0 = *(const float4*)&Ws[kk][tx * 8];
            float4 w1 = *(const float4*)&Ws[kk][tx * 8 + 4];
            float ar[8] = {a0.x, a0.y, a0.z, a0.w, a1.x, a1.y, a1.z, a1.w};
            float wr[8] = {w0.x, w0.y, w0.z, w0.w, w1.x, w1.y, w1.z, w1.w};
            #pragma unroll
            for (int i = 0; i < 8; i++)
                #pragma unroll
                for (int j = 0; j < 8; j++)
                    acc[i][j] += ar[i] * wr[j];
        }
        __syncthreads();
    }
    #pragma unroll
    for (int i = 0; i < 8; i++) {
        int row = bm + ty * 8 + i;
        int col = bn + tx * 8;
        #pragma unroll
        for (int j = 0; j < 8; j++) {
            float v = acc[i][j];
            if (MODE == 1) v = (v > 0.5f) ? 1.f : 0.f;   // spike forward value
            if (MODE == 3) v += bias[col + j];
            acc[i][j] = v;
        }
        *(float4*)(C + (size_t)row * DMODEL + col)     = make_float4(acc[i][0], acc[i][1], acc[i][2], acc[i][3]);
        *(float4*)(C + (size_t)row * DMODEL + col + 4) = make_float4(acc[i][4], acc[i][5], acc[i][6], acc[i][7]);
    }
}

// ---------------- non-causal flash attention ----------------
// grid (T/128, H, B); 128 threads; thread = one query row; Q,O in registers,
// K/V tiles (16 x 64 f32) staged in smem, online softmax. Reads/writes device
// globals directly.
#define TK 16
__global__ __launch_bounds__(128)
void attn_kernel()
{
    __shared__ __align__(16) float4 Ks[TK * 16];
    __shared__ __align__(16) float4 Vs[TK * 16];
    const int tid = threadIdx.x;
    const int b = blockIdx.z, h = blockIdx.y;
    const int q = blockIdx.x * 128 + tid;

    const float* qptr = g_r + ((size_t)(b * TSEQ + q) * DMODEL) + h * DHEAD;
    float4 qv[16];
    #pragma unroll
    for (int i = 0; i < 16; i++) qv[i] = *(const float4*)(qptr + i * 4);
    float4 ov[16];
    #pragma unroll
    for (int i = 0; i < 16; i++) ov[i] = make_float4(0.f, 0.f, 0.f, 0.f);
    float mval = -1e30f, l = 0.f;

    for (int kt = 0; kt < TSEQ; kt += TK) {
        #pragma unroll
        for (int e = 0; e < 2; e++) {
            int i  = tid * 2 + e;
            int kk = i >> 4, d4 = i & 15;
            size_t base = (size_t)(b * TSEQ + kt + kk) * DMODEL + h * DHEAD + d4 * 4;
            Ks[i] = *(const float4*)(g_k + base);
            Vs[i] = *(const float4*)(g_v + base);
        }
        __syncthreads();

        float s[TK];
        float smax = mval;
        #pragma unroll
        for (int kk = 0; kk < TK; kk++) {
            float acc = 0.f;
            #pragma unroll
            for (int d4 = 0; d4 < 16; d4++) {
                float4 kv = Ks[kk * 16 + d4];
                acc += qv[d4].x * kv.x + qv[d4].y * kv.y
                     + qv[d4].z * kv.z + qv[d4].w * kv.w;
            }
            s[kk] = acc * 0.125f;                 // 1/sqrt(64)
            smax = fmaxf(smax, s[kk]);
        }
        float corr = __expf(mval - smax);
        l *= corr;
        #pragma unroll
        for (int i = 0; i < 16; i++) {
            ov[i].x *= corr; ov[i].y *= corr; ov[i].z *= corr; ov[i].w *= corr;
        }
        #pragma unroll
        for (int kk = 0; kk < TK; kk++) {
            float p = __expf(s[kk] - smax);
            l += p;
            #pragma unroll
            for (int d4 = 0; d4 < 16; d4++) {
                float4 vv = Vs[kk * 16 + d4];
                ov[d4].x += p * vv.x; ov[d4].y += p * vv.y;
                ov[d4].z += p * vv.z; ov[d4].w += p * vv.w;
            }
        }
        mval = smax;
        __syncthreads();
    }
    float inv = 1.f / l;
    float* optr = g_o + ((size_t)(b * TSEQ + q) * DMODEL) + h * DHEAD;
    #pragma unroll
    for (int i = 0; i < 16; i++) {
        float4 o = ov[i];
        o.x *= inv; o.y *= inv; o.z *= inv; o.w *= inv;
        *(float4*)(optr + i * 4) = o;
    }
}

// ---------------- launch (only harness pointers cross the boundary) ----------
extern "C" void kernel_launch(void* const* d_in, const int* in_sizes, int n_in,
                              void* d_out, int out_size)
{
    const float* x   = (const float*)d_in[0];
    const int*   tok = (const int*)  d_in[1];
    const float* Wr  = (const float*)d_in[2];
    const float* Wk  = (const float*)d_in[3];
    const float* Wv  = (const float*)d_in[4];
    const float* Wo  = (const float*)d_in[5];
    const float* bo  = (const float*)d_in[6];
    const float* tmk = (const float*)d_in[7];
    const float* tmv = (const float*)d_in[8];
    const float* tmr = (const float*)d_in[9];
    float* out = (float*)d_out;

    zero_cnt_kernel<<<(VOCAB + 255) / 256, 256>>>();
    hist_kernel<<<BT / 256, 256>>>(tok);
    topk_gains_kernel<<<1, 256>>>(tmr, tmk, tmv);

    dim3 gg(DMODEL / 128, BT / 128);   // (8, 32)
    gemm_kernel<0><<<gg, 256>>>(x, Wr, nullptr, nullptr);
    gemm_kernel<1><<<gg, 256>>>(x, Wk, nullptr, nullptr);
    gemm_kernel<2><<<gg, 256>>>(x, Wv, nullptr, nullptr);

    attn_kernel<<<dim3(TSEQ / 128, NHEAD, BATCH), 128>>>();

    gemm_kernel<3><<<gg, 256>>>(nullptr, Wo, bo, out);
}